// round 13
// baseline (speedup 1.0000x reference)
#include <cuda_runtime.h>
#include <cuda_fp16.h>
#include <cstdint>

// ---------------------------------------------------------------------------
#define M_ 16384           // B*S token rows
#define P_ 512             // prototypes (= N)
#define D_ 768             // feature dim (= K)
#define BM 128
#define BN 128
#define BKB 128            // K elements (s8 bytes) per stage = 128 B per row
#define NS (D_ / BKB)      // 6 stages
#define NTH 128            // 4 warps
#define STAGES 3
#define ATILEB 16384
#define STAGEB 32768
#define SMEM_BYTES (STAGES * STAGEB + 128)

#define QSCALE  (127.0f / 5.0f)               // f32 -> s8
#define TWO_S2  (2.0f * (5.0f/127.0f) * (5.0f/127.0f))

__device__ int8_t g_a8[(size_t)M_ * D_];
__device__ int8_t g_b8[(size_t)P_ * D_];
__device__ float  g_xsq[M_];
__device__ float  g_psq[P_];

// ---------------------------------------------------------------------------
// Prep: one pass -> s8 quantized copies + exact f32 row norms + passthrough.
// Block = 256 thr = 16 rows x 16 lanes; each lane reads 12 float4.
// ---------------------------------------------------------------------------
__device__ __forceinline__ uint32_t q4(float4 v) {
    int q0 = __float2int_rn(v.x * QSCALE);
    int q1 = __float2int_rn(v.y * QSCALE);
    int q2 = __float2int_rn(v.z * QSCALE);
    int q3 = __float2int_rn(v.w * QSCALE);
    q0 = max(-127, min(127, q0)); q1 = max(-127, min(127, q1));
    q2 = max(-127, min(127, q2)); q3 = max(-127, min(127, q3));
    return (uint32_t)(q0 & 255) | ((uint32_t)(q1 & 255) << 8)
         | ((uint32_t)(q2 & 255) << 16) | ((uint32_t)(q3 & 255) << 24);
}

__global__ void prep_kernel(const float* __restrict__ X,
                            const float* __restrict__ Pp,
                            float* __restrict__ proto_out) {
    const int r   = threadIdx.x >> 4;
    const int kq  = threadIdx.x & 15;
    const int row = blockIdx.x * 16 + r;
    const float* src;
    int8_t* dst8;
    float* dstn;
    float* passthru = nullptr;
    if (row < M_) {
        src = X + (size_t)row * D_;  dst8 = g_a8 + (size_t)row * D_;  dstn = g_xsq + row;
    } else {
        const int pr = row - M_;
        src = Pp + (size_t)pr * D_;  dst8 = g_b8 + (size_t)pr * D_;   dstn = g_psq + pr;
        passthru = proto_out + (size_t)pr * D_;
    }
    float s = 0.f;
    #pragma unroll
    for (int i = 0; i < 12; i++) {
        float4 v = *reinterpret_cast<const float4*>(src + i * 64 + kq * 4);
        s = fmaf(v.x, v.x, fmaf(v.y, v.y, fmaf(v.z, v.z, fmaf(v.w, v.w, s))));
        *reinterpret_cast<uint32_t*>(dst8 + i * 64 + kq * 4) = q4(v);
        if (passthru) *reinterpret_cast<float4*>(passthru + i * 64 + kq * 4) = v;
    }
    #pragma unroll
    for (int o = 8; o; o >>= 1) s += __shfl_xor_sync(0xffffffffu, s, o);
    if (kq == 0) *dstn = s;
}

// ---------------------------------------------------------------------------
__device__ __forceinline__ void cp_async16(uint32_t d, const void* s) {
    asm volatile("cp.async.cg.shared.global [%0], [%1], 16;" ::"r"(d), "l"(s));
}
#define CP_COMMIT() asm volatile("cp.async.commit_group;" ::: "memory")
#define CP_WAIT_1() asm volatile("cp.async.wait_group 1;" ::: "memory")
#define CP_WAIT_0() asm volatile("cp.async.wait_group 0;" ::: "memory")

#define LDSM_X4(r0, r1, r2, r3, a)                                             \
    asm volatile("ldmatrix.sync.aligned.m8n8.x4.shared.b16 {%0,%1,%2,%3}, [%4];" \
                 : "=r"(r0), "=r"(r1), "=r"(r2), "=r"(r3) : "r"(a))

#define MMA_S8(c0, c1, c2, c3, a0, a1, a2, a3, b0, b1)                         \
    asm volatile("mma.sync.aligned.m16n8k32.row.col.s32.s8.s8.s32 "            \
                 "{%0,%1,%2,%3}, {%4,%5,%6,%7}, {%8,%9}, {%0,%1,%2,%3};"       \
                 : "+r"(c0), "+r"(c1), "+r"(c2), "+r"(c3)                      \
                 : "r"(a0), "r"(a1), "r"(a2), "r"(a3), "r"(b0), "r"(b1))

// ---------------------------------------------------------------------------
// Fused distance GEMM, int8 tensor cores (m16n8k32, s32 accumulate).
// 4 warps (2 M x 2 N), warp tile 64x64, CTA tile 128x128, 2 CTAs/SM.
//   C[m][n] = xsq[m] + psq[n] - 2*s^2 * sum_k qA[m][k] * qB[n][k]
// Smem per tile: row r (128 B = k128 s8), 16B unit u stored at (u ^ (r & 7)).
// Per-lane fragment byte windows are identical to the fp16-k16 layout, so the
// proven LDSM addressing carries over 1:1.
// ---------------------------------------------------------------------------
__global__ __launch_bounds__(NTH, 2)
void dist_s8_kernel(float* __restrict__ C) {
    extern __shared__ __align__(16) char smem[];
    uint32_t sb0;
    asm("{ .reg .u64 t; cvta.to.shared.u64 t, %1; cvt.u32.u64 %0, t; }"
        : "=r"(sb0) : "l"(smem));
    const uint32_t sb = (sb0 + 127u) & ~127u;

    const int tid  = threadIdx.x;
    const int lane = tid & 31;
    const int warp = tid >> 5;
    const int wm   = warp & 1;       // 2 warps along M -> 64 rows each
    const int wn   = warp >> 1;      // 2 warps along N -> 64 cols each
    const int bx   = blockIdx.x;     // N tile (0..3)
    const int by   = blockIdx.y;     // M tile (0..127)

    const int8_t* Ablk = g_a8 + (size_t)by * BM * D_;
    const int8_t* Bblk = g_b8 + (size_t)bx * BN * D_;

    // loader: A 1024 + B 1024 16B-units per stage -> 8 + 8 per thread
    const int lrow = tid >> 3;       // 0..15 (j adds 16)
    const int lu   = tid & 7;
    const uint32_t lsw = (uint32_t)((lu ^ (lrow & 7)) << 4);

    auto load_stage = [&](int s) {
        const uint32_t ab = sb + (uint32_t)(s % STAGES) * STAGEB;
        const uint32_t bb = ab + ATILEB;
        const int kf = s * BKB + lu * 16;
        #pragma unroll
        for (int j = 0; j < 8; j++) {
            const int row = lrow + j * 16;
            cp_async16(ab + (uint32_t)row * 128 + lsw,
                       Ablk + (size_t)row * D_ + kf);
            cp_async16(bb + (uint32_t)row * 128 + lsw,
                       Bblk + (size_t)row * D_ + kf);
        }
    };

    // ldmatrix per-lane components (identical to fp16 version)
    const int rA = wm * 64 + (lane & 7) + ((lane >> 3) & 1) * 8;   // + i*16
    const int uA = lane >> 4;
    const int rB = wn * 64 + (lane & 7) + (lane >> 4) * 8;         // + jp*16
    const int uB = (lane >> 3) & 1;
    const uint32_t swz = (uint32_t)(lane & 7);

    int c[4][8][4];
    #pragma unroll
    for (int i = 0; i < 4; i++)
        #pragma unroll
        for (int j = 0; j < 8; j++)
            #pragma unroll
            for (int q = 0; q < 4; q++) c[i][j][q] = 0;

    uint32_t a[2][4][4], b[2][4][4];

    auto frag_load = [&](int fb, uint32_t ab, uint32_t bb, int kk) {
        #pragma unroll
        for (int i = 0; i < 4; i++) {
            const uint32_t addr = ab + (uint32_t)(rA + i * 16) * 128
                + ((((uint32_t)(kk * 2 + uA)) ^ swz) << 4);
            LDSM_X4(a[fb][i][0], a[fb][i][1], a[fb][i][2], a[fb][i][3], addr);
        }
        #pragma unroll
        for (int jp = 0; jp < 4; jp++) {
            const uint32_t addr = bb + (uint32_t)(rB + jp * 16) * 128
                + ((((uint32_t)(kk * 2 + uB)) ^ swz) << 4);
            LDSM_X4(b[fb][jp][0], b[fb][jp][1], b[fb][jp][2], b[fb][jp][3], addr);
        }
    };

    load_stage(0); CP_COMMIT();
    load_stage(1); CP_COMMIT();

    for (int s = 0; s < NS; ++s) {
        if (s + 1 < NS) { CP_WAIT_1(); } else { CP_WAIT_0(); }
        __syncthreads();                        // stage s visible; buf(s+2) free
        if (s + 2 < NS) { load_stage(s + 2); CP_COMMIT(); }

        const uint32_t ab = sb + (uint32_t)(s % STAGES) * STAGEB;
        const uint32_t bb = ab + ATILEB;

        frag_load(0, ab, bb, 0);
        #pragma unroll
        for (int kk = 0; kk < 4; kk++) {        // 4 x k32 per stage
            const int fb = kk & 1;
            if (kk + 1 < 4) frag_load(fb ^ 1, ab, bb, kk + 1);
            #pragma unroll
            for (int i = 0; i < 4; i++) {
                #pragma unroll
                for (int jp = 0; jp < 4; jp++) {
                    MMA_S8(c[i][jp * 2][0], c[i][jp * 2][1],
                           c[i][jp * 2][2], c[i][jp * 2][3],
                           a[fb][i][0], a[fb][i][1], a[fb][i][2], a[fb][i][3],
                           b[fb][jp][0], b[fb][jp][1]);
                    MMA_S8(c[i][jp * 2 + 1][0], c[i][jp * 2 + 1][1],
                           c[i][jp * 2 + 1][2], c[i][jp * 2 + 1][3],
                           a[fb][i][0], a[fb][i][1], a[fb][i][2], a[fb][i][3],
                           b[fb][jp][2], b[fb][jp][3]);
                }
            }
        }
    }

    // ---- epilogue: dist = xsq + psq - 2*s^2*acc ----
    const int g = lane >> 2;
    const int t = lane & 3;
    #pragma unroll
    for (int i = 0; i < 4; i++) {
        const int mg0 = by * BM + wm * 64 + i * 16 + g;
        const float x0 = g_xsq[mg0];
        const float x1 = g_xsq[mg0 + 8];
        float* row0 = C + (size_t)mg0 * P_;
        float* row1 = C + (size_t)(mg0 + 8) * P_;
        #pragma unroll
        for (int j = 0; j < 8; j++) {
            const int ng = bx * BN + wn * 64 + j * 8 + 2 * t;
            const float p0 = g_psq[ng];
            const float p1 = g_psq[ng + 1];
            float2 v0, v1;
            v0.x = x0 + p0 - TWO_S2 * (float)c[i][j][0];
            v0.y = x0 + p1 - TWO_S2 * (float)c[i][j][1];
            v1.x = x1 + p0 - TWO_S2 * (float)c[i][j][2];
            v1.y = x1 + p1 - TWO_S2 * (float)c[i][j][3];
            *reinterpret_cast<float2*>(row0 + ng) = v0;
            *reinterpret_cast<float2*>(row1 + ng) = v1;
        }
    }
}

// ---------------------------------------------------------------------------
extern "C" void kernel_launch(void* const* d_in, const int* in_sizes, int n_in,
                              void* d_out, int out_size) {
    const float* inputs = (const float*)d_in[0];   // [M_, D_]
    const float* protos = (const float*)d_in[1];   // [P_, D_]
    float* out = (float*)d_out;

    // 1) s8 quantized copies + exact f32 norms + prototype passthrough
    prep_kernel<<<(M_ + P_) / 16, 256>>>(inputs, protos, out + (size_t)M_ * P_);

    // 2) fused distance GEMM (int8 tensor cores)
    cudaFuncSetAttribute(dist_s8_kernel,
                         cudaFuncAttributeMaxDynamicSharedMemorySize, SMEM_BYTES);
    dim3 grid(P_ / BN, M_ / BM);   // (4, 128)
    dist_s8_kernel<<<grid, NTH, SMEM_BYTES>>>(out);
}

// round 14
// speedup vs baseline: 1.9549x; 1.9549x over previous
#include <cuda_runtime.h>
#include <cuda_fp16.h>
#include <cstdint>

// ---------------------------------------------------------------------------
#define M_ 16384           // B*S token rows
#define P_ 512             // prototypes (= N)
#define D_ 768             // feature dim (= K)
#define BM 128
#define BN 128
#define BKH 64             // K halves per stage (128 B per row)
#define NS (D_ / BKH)      // 12 stages
#define NTH 128            // 4 warps
#define STAGES 3
#define ATILEB 16384
#define STAGEB 32768
#define SMEM_BYTES (STAGES * STAGEB + 128)
#define MCH 8192           // M rows per chunk (2 chunks)

__device__ __half g_a16[(size_t)M_ * D_];
__device__ __half g_b16[(size_t)P_ * D_];
__device__ float  g_xsq[M_];
__device__ float  g_psq[P_];

// ---------------------------------------------------------------------------
// prep_P: prototypes -> fp16 copy + exact f32 norms + passthrough (tiny).
// prep_A: one M-chunk of inputs -> fp16 copy + exact f32 norms.
// Block = 256 thr = 16 rows x 16 lanes; each lane reads 12 float4.
// ---------------------------------------------------------------------------
__global__ void prep_P_kernel(const float* __restrict__ Pp,
                              float* __restrict__ proto_out) {
    const int r   = threadIdx.x >> 4;
    const int kq  = threadIdx.x & 15;
    const int row = blockIdx.x * 16 + r;
    const float* src = Pp + (size_t)row * D_;
    __half* dst16 = g_b16 + (size_t)row * D_;
    float* passthru = proto_out + (size_t)row * D_;
    float s = 0.f;
    #pragma unroll
    for (int i = 0; i < 12; i++) {
        float4 v = *reinterpret_cast<const float4*>(src + i * 64 + kq * 4);
        s = fmaf(v.x, v.x, fmaf(v.y, v.y, fmaf(v.z, v.z, fmaf(v.w, v.w, s))));
        __half2 h01 = __floats2half2_rn(v.x, v.y);
        __half2 h23 = __floats2half2_rn(v.z, v.w);
        *reinterpret_cast<uint2*>(dst16 + i * 64 + kq * 4) =
            make_uint2(*reinterpret_cast<uint32_t*>(&h01),
                       *reinterpret_cast<uint32_t*>(&h23));
        *reinterpret_cast<float4*>(passthru + i * 64 + kq * 4) = v;
    }
    #pragma unroll
    for (int o = 8; o; o >>= 1) s += __shfl_xor_sync(0xffffffffu, s, o);
    if (kq == 0) g_psq[row] = s;
}

__global__ void prep_A_kernel(const float* __restrict__ X, int chunk) {
    const int r   = threadIdx.x >> 4;
    const int kq  = threadIdx.x & 15;
    const int row = chunk * MCH + blockIdx.x * 16 + r;
    const float* src = X + (size_t)row * D_;
    __half* dst16 = g_a16 + (size_t)row * D_;
    float s = 0.f;
    #pragma unroll
    for (int i = 0; i < 12; i++) {
        float4 v = *reinterpret_cast<const float4*>(src + i * 64 + kq * 4);
        s = fmaf(v.x, v.x, fmaf(v.y, v.y, fmaf(v.z, v.z, fmaf(v.w, v.w, s))));
        __half2 h01 = __floats2half2_rn(v.x, v.y);
        __half2 h23 = __floats2half2_rn(v.z, v.w);
        *reinterpret_cast<uint2*>(dst16 + i * 64 + kq * 4) =
            make_uint2(*reinterpret_cast<uint32_t*>(&h01),
                       *reinterpret_cast<uint32_t*>(&h23));
    }
    #pragma unroll
    for (int o = 8; o; o >>= 1) s += __shfl_xor_sync(0xffffffffu, s, o);
    if (kq == 0) g_xsq[row] = s;
}

// ---------------------------------------------------------------------------
__device__ __forceinline__ void cp_async16(uint32_t d, const void* s) {
    asm volatile("cp.async.cg.shared.global [%0], [%1], 16;" ::"r"(d), "l"(s));
}
#define CP_COMMIT() asm volatile("cp.async.commit_group;" ::: "memory")
#define CP_WAIT_1() asm volatile("cp.async.wait_group 1;" ::: "memory")
#define CP_WAIT_0() asm volatile("cp.async.wait_group 0;" ::: "memory")

#define LDSM_X4(r0, r1, r2, r3, a)                                             \
    asm volatile("ldmatrix.sync.aligned.m8n8.x4.shared.b16 {%0,%1,%2,%3}, [%4];" \
                 : "=r"(r0), "=r"(r1), "=r"(r2), "=r"(r3) : "r"(a))

#define MMA_F16A(c0, c1, a0, a1, a2, a3, b0, b1)                               \
    asm volatile("mma.sync.aligned.m16n8k16.row.col.f16.f16.f16.f16 "          \
                 "{%0,%1}, {%2,%3,%4,%5}, {%6,%7}, {%0,%1};"                   \
                 : "+r"(c0), "+r"(c1)                                          \
                 : "r"(a0), "r"(a1), "r"(a2), "r"(a3), "r"(b0), "r"(b1))

// ---------------------------------------------------------------------------
// Fused distance GEMM (R12 mainloop, fp16 accumulate), chunked along M.
//   C[m][n] = xsq[m] + psq[n] - 2 * sum_k A16[m][k] * B16[n][k]
// ---------------------------------------------------------------------------
__global__ __launch_bounds__(NTH, 2)
void dist_f16acc_kernel(float* __restrict__ C, int mty0) {
    extern __shared__ __align__(16) char smem[];
    uint32_t sb0;
    asm("{ .reg .u64 t; cvta.to.shared.u64 t, %1; cvt.u32.u64 %0, t; }"
        : "=r"(sb0) : "l"(smem));
    const uint32_t sb = (sb0 + 127u) & ~127u;

    const int tid  = threadIdx.x;
    const int lane = tid & 31;
    const int warp = tid >> 5;
    const int wm   = warp & 1;
    const int wn   = warp >> 1;
    const int bx   = blockIdx.x;               // N tile (0..3)
    const int by   = mty0 + blockIdx.y;        // M tile

    const __half* Ablk = g_a16 + (size_t)by * BM * D_;
    const __half* Bblk = g_b16 + (size_t)bx * BN * D_;

    const int lrow = tid >> 3;
    const int lu   = tid & 7;
    const uint32_t lsw = (uint32_t)((lu ^ (lrow & 7)) << 4);

    auto load_stage = [&](int s) {
        const uint32_t ab = sb + (uint32_t)(s % STAGES) * STAGEB;
        const uint32_t bb = ab + ATILEB;
        const int kf = s * BKH + lu * 8;
        #pragma unroll
        for (int j = 0; j < 8; j++) {
            const int row = lrow + j * 16;
            cp_async16(ab + (uint32_t)row * 128 + lsw,
                       Ablk + (size_t)row * D_ + kf);
            cp_async16(bb + (uint32_t)row * 128 + lsw,
                       Bblk + (size_t)row * D_ + kf);
        }
    };

    const int rA = wm * 64 + (lane & 7) + ((lane >> 3) & 1) * 8;
    const int uA = lane >> 4;
    const int rB = wn * 64 + (lane & 7) + (lane >> 4) * 8;
    const int uB = (lane >> 3) & 1;
    const uint32_t swz = (uint32_t)(lane & 7);

    uint32_t c[4][8][2];
    #pragma unroll
    for (int i = 0; i < 4; i++)
        #pragma unroll
        for (int j = 0; j < 8; j++) { c[i][j][0] = 0u; c[i][j][1] = 0u; }

    uint32_t a[2][4][4], b[2][4][4];

    auto frag_load = [&](int fb, uint32_t ab, uint32_t bb, int kk) {
        #pragma unroll
        for (int i = 0; i < 4; i++) {
            const uint32_t addr = ab + (uint32_t)(rA + i * 16) * 128
                + ((((uint32_t)(kk * 2 + uA)) ^ swz) << 4);
            LDSM_X4(a[fb][i][0], a[fb][i][1], a[fb][i][2], a[fb][i][3], addr);
        }
        #pragma unroll
        for (int jp = 0; jp < 4; jp++) {
            const uint32_t addr = bb + (uint32_t)(rB + jp * 16) * 128
                + ((((uint32_t)(kk * 2 + uB)) ^ swz) << 4);
            LDSM_X4(b[fb][jp][0], b[fb][jp][1], b[fb][jp][2], b[fb][jp][3], addr);
        }
    };

    load_stage(0); CP_COMMIT();
    load_stage(1); CP_COMMIT();

    for (int s = 0; s < NS; ++s) {
        if (s + 1 < NS) { CP_WAIT_1(); } else { CP_WAIT_0(); }
        __syncthreads();
        if (s + 2 < NS) { load_stage(s + 2); CP_COMMIT(); }

        const uint32_t ab = sb + (uint32_t)(s % STAGES) * STAGEB;
        const uint32_t bb = ab + ATILEB;

        frag_load(0, ab, bb, 0);
        #pragma unroll
        for (int kk = 0; kk < 4; kk++) {
            const int fb = kk & 1;
            if (kk + 1 < 4) frag_load(fb ^ 1, ab, bb, kk + 1);
            #pragma unroll
            for (int i = 0; i < 4; i++) {
                #pragma unroll
                for (int jp = 0; jp < 4; jp++) {
                    MMA_F16A(c[i][jp * 2][0], c[i][jp * 2][1],
                             a[fb][i][0], a[fb][i][1], a[fb][i][2], a[fb][i][3],
                             b[fb][jp][0], b[fb][jp][1]);
                    MMA_F16A(c[i][jp * 2 + 1][0], c[i][jp * 2 + 1][1],
                             a[fb][i][0], a[fb][i][1], a[fb][i][2], a[fb][i][3],
                             b[fb][jp][2], b[fb][jp][3]);
                }
            }
        }
    }

    const int g = lane >> 2;
    const int t = lane & 3;
    #pragma unroll
    for (int i = 0; i < 4; i++) {
        const int mg0 = by * BM + wm * 64 + i * 16 + g;
        const float x0 = g_xsq[mg0];
        const float x1 = g_xsq[mg0 + 8];
        float* row0 = C + (size_t)mg0 * P_;
        float* row1 = C + (size_t)(mg0 + 8) * P_;
        #pragma unroll
        for (int j = 0; j < 8; j++) {
            const int ng = bx * BN + wn * 64 + j * 8 + 2 * t;
            const float p0 = g_psq[ng];
            const float p1 = g_psq[ng + 1];
            const float2 f0 = __half22float2(*reinterpret_cast<__half2*>(&c[i][j][0]));
            const float2 f1 = __half22float2(*reinterpret_cast<__half2*>(&c[i][j][1]));
            float2 v0, v1;
            v0.x = x0 + p0 - 2.f * f0.x;
            v0.y = x0 + p1 - 2.f * f0.y;
            v1.x = x1 + p0 - 2.f * f1.x;
            v1.y = x1 + p1 - 2.f * f1.y;
            *reinterpret_cast<float2*>(row0 + ng) = v0;
            *reinterpret_cast<float2*>(row1 + ng) = v1;
        }
    }
}

// ---------------------------------------------------------------------------
// Launch: fork prep onto side streams so GEMM chunk 0 overlaps prep chunk 1.
// Streams/events are host resources created once (no device allocations).
// Graph shape is identical on every call.
// ---------------------------------------------------------------------------
extern "C" void kernel_launch(void* const* d_in, const int* in_sizes, int n_in,
                              void* d_out, int out_size) {
    const float* inputs = (const float*)d_in[0];   // [M_, D_]
    const float* protos = (const float*)d_in[1];   // [P_, D_]
    float* out = (float*)d_out;

    static cudaStream_t sP = nullptr, sG = nullptr;
    static cudaEvent_t eFork, eA0, eA1, eG0;
    static bool init_done = false;
    if (!init_done) {
        cudaStreamCreateWithFlags(&sP, cudaStreamNonBlocking);
        cudaStreamCreateWithFlags(&sG, cudaStreamNonBlocking);
        cudaEventCreateWithFlags(&eFork, cudaEventDisableTiming);
        cudaEventCreateWithFlags(&eA0,   cudaEventDisableTiming);
        cudaEventCreateWithFlags(&eA1,   cudaEventDisableTiming);
        cudaEventCreateWithFlags(&eG0,   cudaEventDisableTiming);
        cudaFuncSetAttribute(dist_f16acc_kernel,
                             cudaFuncAttributeMaxDynamicSharedMemorySize,
                             SMEM_BYTES);
        init_done = true;
    }

    // fork side streams off the (capture) default stream
    cudaEventRecord(eFork, 0);
    cudaStreamWaitEvent(sP, eFork, 0);
    cudaStreamWaitEvent(sG, eFork, 0);

    // prep chain on sP
    prep_P_kernel<<<P_ / 16, 256, 0, sP>>>(protos, out + (size_t)M_ * P_);
    prep_A_kernel<<<MCH / 16, 256, 0, sP>>>(inputs, 0);
    cudaEventRecord(eA0, sP);
    prep_A_kernel<<<MCH / 16, 256, 0, sP>>>(inputs, 1);
    cudaEventRecord(eA1, sP);

    // GEMM chunk 0 on sG (after prep_P + prep_A(0))
    cudaStreamWaitEvent(sG, eA0, 0);
    {
        dim3 grid(P_ / BN, MCH / BM);   // (4, 64)
        dist_f16acc_kernel<<<grid, NTH, SMEM_BYTES, sG>>>(out, 0);
    }
    cudaEventRecord(eG0, sG);

    // GEMM chunk 1 on default stream (after prep_A(1)); joins sP
    cudaStreamWaitEvent(0, eA1, 0);
    {
        dim3 grid(P_ / BN, MCH / BM);   // (4, 64)
        dist_f16acc_kernel<<<grid, NTH, SMEM_BYTES, 0>>>(out, MCH / BM);
    }
    // join sG back into the default stream
    cudaStreamWaitEvent(0, eG0, 0);
}

// round 15
// speedup vs baseline: 2.2192x; 1.1352x over previous
#include <cuda_runtime.h>
#include <cuda_fp16.h>
#include <cstdint>

// ---------------------------------------------------------------------------
#define M_ 16384           // B*S token rows
#define P_ 512             // prototypes (= N)
#define D_ 768             // feature dim (= K)
#define BM 128
#define BN 128
#define BKH 64             // K halves per stage (128 B per row)
#define NS (D_ / BKH)      // 12 stages
#define NTH 128            // 4 warps
#define STAGES 2
#define ATILEB 16384
#define STAGEB 32768
#define SMEM_BYTES (STAGES * STAGEB + 128)

__device__ __half g_a16[(size_t)M_ * D_];
__device__ __half g_b16[(size_t)P_ * D_];
__device__ float  g_xsq[M_];
__device__ float  g_psq[P_];

// ---------------------------------------------------------------------------
// Prep: one pass -> fp16 copies + exact f32 row norms + prototype passthrough.
// ---------------------------------------------------------------------------
__global__ void prep_kernel(const float* __restrict__ X,
                            const float* __restrict__ Pp,
                            float* __restrict__ proto_out) {
    const int r   = threadIdx.x >> 4;
    const int kq  = threadIdx.x & 15;
    const int row = blockIdx.x * 16 + r;
    const float* src;
    __half* dst16;
    float* dstn;
    float* passthru = nullptr;
    if (row < M_) {
        src = X + (size_t)row * D_;  dst16 = g_a16 + (size_t)row * D_;  dstn = g_xsq + row;
    } else {
        const int pr = row - M_;
        src = Pp + (size_t)pr * D_;  dst16 = g_b16 + (size_t)pr * D_;   dstn = g_psq + pr;
        passthru = proto_out + (size_t)pr * D_;
    }
    float s = 0.f;
    #pragma unroll
    for (int i = 0; i < 12; i++) {
        float4 v = *reinterpret_cast<const float4*>(src + i * 64 + kq * 4);
        s = fmaf(v.x, v.x, fmaf(v.y, v.y, fmaf(v.z, v.z, fmaf(v.w, v.w, s))));
        __half2 h01 = __floats2half2_rn(v.x, v.y);
        __half2 h23 = __floats2half2_rn(v.z, v.w);
        *reinterpret_cast<uint2*>(dst16 + i * 64 + kq * 4) =
            make_uint2(*reinterpret_cast<uint32_t*>(&h01),
                       *reinterpret_cast<uint32_t*>(&h23));
        if (passthru) *reinterpret_cast<float4*>(passthru + i * 64 + kq * 4) = v;
    }
    #pragma unroll
    for (int o = 8; o; o >>= 1) s += __shfl_xor_sync(0xffffffffu, s, o);
    if (kq == 0) *dstn = s;
}

// ---------------------------------------------------------------------------
__device__ __forceinline__ void cp_async16(uint32_t d, const void* s) {
    asm volatile("cp.async.cg.shared.global [%0], [%1], 16;" ::"r"(d), "l"(s));
}
#define CP_COMMIT() asm volatile("cp.async.commit_group;" ::: "memory")
#define CP_WAIT_1() asm volatile("cp.async.wait_group 1;" ::: "memory")
#define CP_WAIT_0() asm volatile("cp.async.wait_group 0;" ::: "memory")

#define LDSM_X4(r0, r1, r2, r3, a)                                             \
    asm volatile("ldmatrix.sync.aligned.m8n8.x4.shared.b16 {%0,%1,%2,%3}, [%4];" \
                 : "=r"(r0), "=r"(r1), "=r"(r2), "=r"(r3) : "r"(a))

#define MMA_F16A(c0, c1, a0, a1, a2, a3, b0, b1)                               \
    asm volatile("mma.sync.aligned.m16n8k16.row.col.f16.f16.f16.f16 "          \
                 "{%0,%1}, {%2,%3,%4,%5}, {%6,%7}, {%0,%1};"                   \
                 : "+r"(c0), "+r"(c1)                                          \
                 : "r"(a0), "r"(a1), "r"(a2), "r"(a3), "r"(b0), "r"(b1))

// ---------------------------------------------------------------------------
// Fused distance GEMM, fp16 tensor cores, fp16 accumulate.
// 4 warps (2 M x 2 N), warp tile 64x64, CTA tile 128x128.
// 2-stage cp.async pipeline -> 64 KB smem -> 3 CTAs/SM (12 warps/SM).
//   C[m][n] = xsq[m] + psq[n] - 2 * sum_k A16[m][k] * B16[n][k]
// Smem per tile: row r (128 B), 16B unit u stored at (u ^ (r & 7)).
// ---------------------------------------------------------------------------
__global__ __launch_bounds__(NTH, 3)
void dist_f16acc3_kernel(float* __restrict__ C) {
    extern __shared__ __align__(16) char smem[];
    uint32_t sb0;
    asm("{ .reg .u64 t; cvta.to.shared.u64 t, %1; cvt.u32.u64 %0, t; }"
        : "=r"(sb0) : "l"(smem));
    const uint32_t sb = (sb0 + 127u) & ~127u;

    const int tid  = threadIdx.x;
    const int lane = tid & 31;
    const int warp = tid >> 5;
    const int wm   = warp & 1;       // 2 warps along M -> 64 rows each
    const int wn   = warp >> 1;      // 2 warps along N -> 64 cols each
    const int bx   = blockIdx.x;     // N tile (0..3)
    const int by   = blockIdx.y;     // M tile (0..127)

    const __half* Ablk = g_a16 + (size_t)by * BM * D_;
    const __half* Bblk = g_b16 + (size_t)bx * BN * D_;

    // loader: A 1024 + B 1024 16B-units per stage -> 8 + 8 per thread
    const int lrow = tid >> 3;       // 0..15 (j adds 16)
    const int lu   = tid & 7;
    const uint32_t lsw = (uint32_t)((lu ^ (lrow & 7)) << 4);

    auto load_stage = [&](int s) {
        const uint32_t ab = sb + (uint32_t)(s & 1) * STAGEB;
        const uint32_t bb = ab + ATILEB;
        const int kf = s * BKH + lu * 8;
        #pragma unroll
        for (int j = 0; j < 8; j++) {
            const int row = lrow + j * 16;
            cp_async16(ab + (uint32_t)row * 128 + lsw,
                       Ablk + (size_t)row * D_ + kf);
            cp_async16(bb + (uint32_t)row * 128 + lsw,
                       Bblk + (size_t)row * D_ + kf);
        }
    };

    // ldmatrix per-lane components
    const int rA = wm * 64 + (lane & 7) + ((lane >> 3) & 1) * 8;   // + i*16
    const int uA = lane >> 4;
    const int rB = wn * 64 + (lane & 7) + (lane >> 4) * 8;         // + jp*16
    const int uB = (lane >> 3) & 1;
    const uint32_t swz = (uint32_t)(lane & 7);

    uint32_t c[4][8][2];             // fp16x2 accumulators
    #pragma unroll
    for (int i = 0; i < 4; i++)
        #pragma unroll
        for (int j = 0; j < 8; j++) { c[i][j][0] = 0u; c[i][j][1] = 0u; }

    uint32_t a[2][4][4], b[2][4][4];

    auto frag_load = [&](int fb, uint32_t ab, uint32_t bb, int kk) {
        #pragma unroll
        for (int i = 0; i < 4; i++) {
            const uint32_t addr = ab + (uint32_t)(rA + i * 16) * 128
                + ((((uint32_t)(kk * 2 + uA)) ^ swz) << 4);
            LDSM_X4(a[fb][i][0], a[fb][i][1], a[fb][i][2], a[fb][i][3], addr);
        }
        #pragma unroll
        for (int jp = 0; jp < 4; jp++) {
            const uint32_t addr = bb + (uint32_t)(rB + jp * 16) * 128
                + ((((uint32_t)(kk * 2 + uB)) ^ swz) << 4);
            LDSM_X4(b[fb][jp][0], b[fb][jp][1], b[fb][jp][2], b[fb][jp][3], addr);
        }
    };

    load_stage(0); CP_COMMIT();

    for (int s = 0; s < NS; ++s) {
        // issue next stage into the buffer freed by the trailing barrier of s-1
        if (s + 1 < NS) { load_stage(s + 1); CP_COMMIT(); CP_WAIT_1(); }
        else            { CP_WAIT_0(); }
        __syncthreads();                        // stage s visible to all warps

        const uint32_t ab = sb + (uint32_t)(s & 1) * STAGEB;
        const uint32_t bb = ab + ATILEB;

        frag_load(0, ab, bb, 0);
        #pragma unroll
        for (int kk = 0; kk < 4; kk++) {        // 4 x k16 per stage
            const int fb = kk & 1;
            if (kk + 1 < 4) frag_load(fb ^ 1, ab, bb, kk + 1);
            #pragma unroll
            for (int i = 0; i < 4; i++) {
                #pragma unroll
                for (int jp = 0; jp < 4; jp++) {
                    MMA_F16A(c[i][jp * 2][0], c[i][jp * 2][1],
                             a[fb][i][0], a[fb][i][1], a[fb][i][2], a[fb][i][3],
                             b[fb][jp][0], b[fb][jp][1]);
                    MMA_F16A(c[i][jp * 2 + 1][0], c[i][jp * 2 + 1][1],
                             a[fb][i][0], a[fb][i][1], a[fb][i][2], a[fb][i][3],
                             b[fb][jp][2], b[fb][jp][3]);
                }
            }
        }
        __syncthreads();                        // buf (s&1) free for stage s+2
    }

    // ---- epilogue: dist = xsq + psq - 2*cross ----
    const int g = lane >> 2;
    const int t = lane & 3;
    #pragma unroll
    for (int i = 0; i < 4; i++) {
        const int mg0 = by * BM + wm * 64 + i * 16 + g;
        const float x0 = g_xsq[mg0];
        const float x1 = g_xsq[mg0 + 8];
        float* row0 = C + (size_t)mg0 * P_;
        float* row1 = C + (size_t)(mg0 + 8) * P_;
        #pragma unroll
        for (int j = 0; j < 8; j++) {
            const int ng = bx * BN + wn * 64 + j * 8 + 2 * t;
            const float p0 = g_psq[ng];
            const float p1 = g_psq[ng + 1];
            const float2 f0 = __half22float2(*reinterpret_cast<__half2*>(&c[i][j][0]));
            const float2 f1 = __half22float2(*reinterpret_cast<__half2*>(&c[i][j][1]));
            float2 v0, v1;
            v0.x = x0 + p0 - 2.f * f0.x;
            v0.y = x0 + p1 - 2.f * f0.y;
            v1.x = x1 + p0 - 2.f * f1.x;
            v1.y = x1 + p1 - 2.f * f1.y;
            *reinterpret_cast<float2*>(row0 + ng) = v0;
            *reinterpret_cast<float2*>(row1 + ng) = v1;
        }
    }
}

// ---------------------------------------------------------------------------
extern "C" void kernel_launch(void* const* d_in, const int* in_sizes, int n_in,
                              void* d_out, int out_size) {
    const float* inputs = (const float*)d_in[0];   // [M_, D_]
    const float* protos = (const float*)d_in[1];   // [P_, D_]
    float* out = (float*)d_out;

    // 1) fp16 copies + exact f32 norms + prototype passthrough (single pass)
    prep_kernel<<<(M_ + P_) / 16, 256>>>(inputs, protos, out + (size_t)M_ * P_);

    // 2) fused distance GEMM (fp16 accumulate, 3 CTAs/SM)
    cudaFuncSetAttribute(dist_f16acc3_kernel,
                         cudaFuncAttributeMaxDynamicSharedMemorySize, SMEM_BYTES);
    dim3 grid(P_ / BN, M_ / BM);   // (4, 128)
    dist_f16acc3_kernel<<<grid, NTH, SMEM_BYTES>>>(out);
}

// round 16
// speedup vs baseline: 2.3992x; 1.0811x over previous
#include <cuda_runtime.h>
#include <cuda_fp16.h>
#include <cstdint>

// ---------------------------------------------------------------------------
#define M_ 16384           // B*S token rows
#define P_ 512             // prototypes (= N)
#define D_ 768             // feature dim (= K)
#define BM 128
#define BN 64
#define BKH 64             // K halves per stage (128 B per row)
#define NS (D_ / BKH)      // 12 stages
#define NTH 128            // 4 warps
#define ATILEB 16384       // 128 rows x 128 B
#define BTILEB 8192        // 64 rows x 128 B
#define STAGEB (ATILEB + BTILEB)
#define SMEM_BYTES (2 * STAGEB + 128)

__device__ __half g_a16[(size_t)M_ * D_];
__device__ __half g_b16[(size_t)P_ * D_];
__device__ float  g_xsq[M_];
__device__ float  g_psq[P_];

// ---------------------------------------------------------------------------
// Prep: one pass -> fp16 copies + exact f32 row norms + prototype passthrough.
// ---------------------------------------------------------------------------
__global__ void prep_kernel(const float* __restrict__ X,
                            const float* __restrict__ Pp,
                            float* __restrict__ proto_out) {
    const int r   = threadIdx.x >> 4;
    const int kq  = threadIdx.x & 15;
    const int row = blockIdx.x * 16 + r;
    const float* src;
    __half* dst16;
    float* dstn;
    float* passthru = nullptr;
    if (row < M_) {
        src = X + (size_t)row * D_;  dst16 = g_a16 + (size_t)row * D_;  dstn = g_xsq + row;
    } else {
        const int pr = row - M_;
        src = Pp + (size_t)pr * D_;  dst16 = g_b16 + (size_t)pr * D_;   dstn = g_psq + pr;
        passthru = proto_out + (size_t)pr * D_;
    }
    float s = 0.f;
    #pragma unroll
    for (int i = 0; i < 12; i++) {
        float4 v = *reinterpret_cast<const float4*>(src + i * 64 + kq * 4);
        s = fmaf(v.x, v.x, fmaf(v.y, v.y, fmaf(v.z, v.z, fmaf(v.w, v.w, s))));
        __half2 h01 = __floats2half2_rn(v.x, v.y);
        __half2 h23 = __floats2half2_rn(v.z, v.w);
        *reinterpret_cast<uint2*>(dst16 + i * 64 + kq * 4) =
            make_uint2(*reinterpret_cast<uint32_t*>(&h01),
                       *reinterpret_cast<uint32_t*>(&h23));
        if (passthru) *reinterpret_cast<float4*>(passthru + i * 64 + kq * 4) = v;
    }
    #pragma unroll
    for (int o = 8; o; o >>= 1) s += __shfl_xor_sync(0xffffffffu, s, o);
    if (kq == 0) *dstn = s;
}

// ---------------------------------------------------------------------------
__device__ __forceinline__ void cp_async16(uint32_t d, const void* s) {
    asm volatile("cp.async.cg.shared.global [%0], [%1], 16;" ::"r"(d), "l"(s));
}
#define CP_COMMIT() asm volatile("cp.async.commit_group;" ::: "memory")
#define CP_WAIT_1() asm volatile("cp.async.wait_group 1;" ::: "memory")
#define CP_WAIT_0() asm volatile("cp.async.wait_group 0;" ::: "memory")

#define LDSM_X4(r0, r1, r2, r3, a)                                             \
    asm volatile("ldmatrix.sync.aligned.m8n8.x4.shared.b16 {%0,%1,%2,%3}, [%4];" \
                 : "=r"(r0), "=r"(r1), "=r"(r2), "=r"(r3) : "r"(a))

#define MMA_F16A(c0, c1, a0, a1, a2, a3, b0, b1)                               \
    asm volatile("mma.sync.aligned.m16n8k16.row.col.f16.f16.f16.f16 "          \
                 "{%0,%1}, {%2,%3,%4,%5}, {%6,%7}, {%0,%1};"                   \
                 : "+r"(c0), "+r"(c1)                                          \
                 : "r"(a0), "r"(a1), "r"(a2), "r"(a3), "r"(b0), "r"(b1))

// ---------------------------------------------------------------------------
// Fused distance GEMM, fp16 tensor cores, fp16 accumulate.
// CTA tile 128x64, 4 warps (2 M x 2 N), warp tile 64x32.
// 2-stage pipeline, 48 KB smem -> 4 CTAs/SM (16 warps/SM, 4 barrier domains).
//   C[m][n] = xsq[m] + psq[n] - 2 * sum_k A16[m][k] * B16[n][k]
// Smem per tile: row r (128 B), 16B unit u stored at (u ^ (r & 7)).
// ---------------------------------------------------------------------------
__global__ __launch_bounds__(NTH, 4)
void dist_f16acc4_kernel(float* __restrict__ C) {
    extern __shared__ __align__(16) char smem[];
    uint32_t sb0;
    asm("{ .reg .u64 t; cvta.to.shared.u64 t, %1; cvt.u32.u64 %0, t; }"
        : "=r"(sb0) : "l"(smem));
    const uint32_t sb = (sb0 + 127u) & ~127u;

    const int tid  = threadIdx.x;
    const int lane = tid & 31;
    const int warp = tid >> 5;
    const int wm   = warp & 1;       // 2 warps along M -> 64 rows each
    const int wn   = warp >> 1;      // 2 warps along N -> 32 cols each
    const int bx   = blockIdx.x;     // N tile (0..7)
    const int by   = blockIdx.y;     // M tile (0..127)

    const __half* Ablk = g_a16 + (size_t)by * BM * D_;
    const __half* Bblk = g_b16 + (size_t)bx * BN * D_;

    // loader: A 1024 + B 512 16B-units per stage -> 8 + 4 per thread
    const int lrow = tid >> 3;       // 0..15
    const int lu   = tid & 7;
    const uint32_t lsw = (uint32_t)((lu ^ (lrow & 7)) << 4);

    auto load_stage = [&](int s) {
        const uint32_t ab = sb + (uint32_t)(s & 1) * STAGEB;
        const uint32_t bb = ab + ATILEB;
        const int kf = s * BKH + lu * 8;
        #pragma unroll
        for (int j = 0; j < 8; j++) {          // A: rows lrow + 16j
            const int row = lrow + j * 16;
            cp_async16(ab + (uint32_t)row * 128 + lsw,
                       Ablk + (size_t)row * D_ + kf);
        }
        #pragma unroll
        for (int j = 0; j < 4; j++) {          // B: rows lrow + 16j (0..63)
            const int row = lrow + j * 16;
            cp_async16(bb + (uint32_t)row * 128 + lsw,
                       Bblk + (size_t)row * D_ + kf);
        }
    };

    // ldmatrix per-lane components
    const int rA = wm * 64 + (lane & 7) + ((lane >> 3) & 1) * 8;   // + i*16
    const int uA = lane >> 4;
    const int rB = wn * 32 + (lane & 7) + (lane >> 4) * 8;         // + jp*16
    const int uB = (lane >> 3) & 1;
    const uint32_t swz = (uint32_t)(lane & 7);

    uint32_t c[4][4][2];             // fp16x2 accumulators (64x32 warp tile)
    #pragma unroll
    for (int i = 0; i < 4; i++)
        #pragma unroll
        for (int j = 0; j < 4; j++) { c[i][j][0] = 0u; c[i][j][1] = 0u; }

    uint32_t a[2][4][4], b[2][2][4];

    auto frag_load = [&](int fb, uint32_t ab, uint32_t bb, int kk) {
        #pragma unroll
        for (int i = 0; i < 4; i++) {
            const uint32_t addr = ab + (uint32_t)(rA + i * 16) * 128
                + ((((uint32_t)(kk * 2 + uA)) ^ swz) << 4);
            LDSM_X4(a[fb][i][0], a[fb][i][1], a[fb][i][2], a[fb][i][3], addr);
        }
        #pragma unroll
        for (int jp = 0; jp < 2; jp++) {
            const uint32_t addr = bb + (uint32_t)(rB + jp * 16) * 128
                + ((((uint32_t)(kk * 2 + uB)) ^ swz) << 4);
            LDSM_X4(b[fb][jp][0], b[fb][jp][1], b[fb][jp][2], b[fb][jp][3], addr);
        }
    };

    load_stage(0); CP_COMMIT();

    for (int s = 0; s < NS; ++s) {
        if (s + 1 < NS) { load_stage(s + 1); CP_COMMIT(); CP_WAIT_1(); }
        else            { CP_WAIT_0(); }
        __syncthreads();                        // stage s visible

        const uint32_t ab = sb + (uint32_t)(s & 1) * STAGEB;
        const uint32_t bb = ab + ATILEB;

        frag_load(0, ab, bb, 0);
        #pragma unroll
        for (int kk = 0; kk < 4; kk++) {        // 4 x k16 per stage
            const int fb = kk & 1;
            if (kk + 1 < 4) frag_load(fb ^ 1, ab, bb, kk + 1);
            #pragma unroll
            for (int i = 0; i < 4; i++) {
                #pragma unroll
                for (int jp = 0; jp < 2; jp++) {
                    MMA_F16A(c[i][jp * 2][0], c[i][jp * 2][1],
                             a[fb][i][0], a[fb][i][1], a[fb][i][2], a[fb][i][3],
                             b[fb][jp][0], b[fb][jp][1]);
                    MMA_F16A(c[i][jp * 2 + 1][0], c[i][jp * 2 + 1][1],
                             a[fb][i][0], a[fb][i][1], a[fb][i][2], a[fb][i][3],
                             b[fb][jp][2], b[fb][jp][3]);
                }
            }
        }
        __syncthreads();                        // buf (s&1) free for stage s+2
    }

    // ---- epilogue: dist = xsq + psq - 2*cross ----
    const int g = lane >> 2;
    const int t = lane & 3;
    #pragma unroll
    for (int i = 0; i < 4; i++) {
        const int mg0 = by * BM + wm * 64 + i * 16 + g;
        const float x0 = g_xsq[mg0];
        const float x1 = g_xsq[mg0 + 8];
        float* row0 = C + (size_t)mg0 * P_;
        float* row1 = C + (size_t)(mg0 + 8) * P_;
        #pragma unroll
        for (int j = 0; j < 4; j++) {
            const int ng = bx * BN + wn * 32 + j * 8 + 2 * t;
            const float p0 = g_psq[ng];
            const float p1 = g_psq[ng + 1];
            const float2 f0 = __half22float2(*reinterpret_cast<__half2*>(&c[i][j][0]));
            const float2 f1 = __half22float2(*reinterpret_cast<__half2*>(&c[i][j][1]));
            float2 v0, v1;
            v0.x = x0 + p0 - 2.f * f0.x;
            v0.y = x0 + p1 - 2.f * f0.y;
            v1.x = x1 + p0 - 2.f * f1.x;
            v1.y = x1 + p1 - 2.f * f1.y;
            *reinterpret_cast<float2*>(row0 + ng) = v0;
            *reinterpret_cast<float2*>(row1 + ng) = v1;
        }
    }
}

// ---------------------------------------------------------------------------
extern "C" void kernel_launch(void* const* d_in, const int* in_sizes, int n_in,
                              void* d_out, int out_size) {
    const float* inputs = (const float*)d_in[0];   // [M_, D_]
    const float* protos = (const float*)d_in[1];   // [P_, D_]
    float* out = (float*)d_out;

    // 1) fp16 copies + exact f32 norms + prototype passthrough (single pass)
    prep_kernel<<<(M_ + P_) / 16, 256>>>(inputs, protos, out + (size_t)M_ * P_);

    // 2) fused distance GEMM (fp16 accumulate, 4 CTAs/SM)
    cudaFuncSetAttribute(dist_f16acc4_kernel,
                         cudaFuncAttributeMaxDynamicSharedMemorySize, SMEM_BYTES);
    dim3 grid(P_ / BN, M_ / BM);   // (8, 128)
    dist_f16acc4_kernel<<<grid, NTH, SMEM_BYTES>>>(out);
}